// round 1
// baseline (speedup 1.0000x reference)
#include <cuda_runtime.h>
#include <math.h>

// ---------------- problem constants ----------------
#define B_     16
#define N_     196
#define E_     512
#define H_     8
#define HD_    64
#define C_     2048
#define HDC_   256
#define FN_    784            // 4*N
#define BN_    3136           // B*N
#define NE_    100352         // N*E
#define FNE_   401408         // 4N*E
#define BNE_   1605632        // B*N*E
#define SCHZ_  38416          // 196*196
#define ATTZ_  153664         // 196*784

// ---------------- scratch (static device memory; no allocation) ----------------
__device__ float g_cx  [4*BN_*E_];       // [4,B,N,E] per-branch LN
__device__ float g_ec  [BN_*C_];         // [B,N,C]   concat LN
__device__ float g_qc  [BN_*C_];
__device__ float g_kc  [BN_*C_];
__device__ float g_vc  [BN_*C_];
__device__ float g_sch [B_*H_*N_*N_];    // channel scores
__device__ float g_t   [BN_*C_];         // s@v  (as [B,N,C])
__device__ float g_that[BN_*C_];         // T_hat
__device__ float g_kvs [B_*FN_*E_];      // KV_S
__device__ float g_Q   [4*BN_*E_];
__device__ float g_K   [B_*FN_*E_];
__device__ float g_V   [B_*FN_*E_];
__device__ float g_attn[512u*196*784];   // [g,b,h,N,4N]  315 MB
__device__ float g_mean[512];
__device__ float g_rstd[512];
__device__ float g_ctx [4*B_*H_*N_*HD_]; // [g,b,h,n,d]
__device__ float g_cm0 [BN_*E_];         // branch-0 permuted ctx
__device__ float g_h   [4*BN_*E_];       // residual-1 output
__device__ float g_xln [4*BN_*E_];
__device__ float g_x1  [4*BN_*2048];     // fc1 output
__device__ float g_qwT [4*N_*N_];
__device__ float g_kwT [FN_*FN_];
__device__ float g_vwT [FN_*FN_];

// ---------------- reductions ----------------
__device__ __forceinline__ float block_sum(float v, float* sh) {
    int tid = threadIdx.x;
    #pragma unroll
    for (int o = 16; o > 0; o >>= 1) v += __shfl_down_sync(0xffffffffu, v, o);
    if ((tid & 31) == 0) sh[tid >> 5] = v;
    __syncthreads();
    if (tid < 32) {
        float t = (tid < (int)(blockDim.x >> 5)) ? sh[tid] : 0.f;
        #pragma unroll
        for (int o = 16; o > 0; o >>= 1) t += __shfl_down_sync(0xffffffffu, t, o);
        if (tid == 0) sh[0] = t;
    }
    __syncthreads();
    float r = sh[0];
    __syncthreads();
    return r;
}

__device__ __forceinline__ float block_max(float v, float* sh) {
    int tid = threadIdx.x;
    #pragma unroll
    for (int o = 16; o > 0; o >>= 1) v = fmaxf(v, __shfl_down_sync(0xffffffffu, v, o));
    if ((tid & 31) == 0) sh[tid >> 5] = v;
    __syncthreads();
    if (tid < 32) {
        float t = (tid < (int)(blockDim.x >> 5)) ? sh[tid] : -INFINITY;
        #pragma unroll
        for (int o = 16; o > 0; o >>= 1) t = fmaxf(t, __shfl_down_sync(0xffffffffu, t, o));
        if (tid == 0) sh[0] = t;
    }
    __syncthreads();
    float r = sh[0];
    __syncthreads();
    return r;
}

// ---------------- fused LN: per-branch cx + concat ec ----------------
__global__ void __launch_bounds__(256) ln_fused_kernel(
    const float* __restrict__ e1, const float* __restrict__ e2,
    const float* __restrict__ e3, const float* __restrict__ e4,
    const float* __restrict__ lag, const float* __restrict__ lab,
    const float* __restrict__ lcg, const float* __restrict__ lcb,
    float* __restrict__ cx, float* __restrict__ ec)
{
    __shared__ float sh[32];
    int token = blockIdx.x;
    int tid = threadIdx.x;
    const float* es[4] = {e1, e2, e3, e4};
    float x[4][2], mg[4], rg[4];
    float stot = 0.f, sstot = 0.f;
    #pragma unroll
    for (int g = 0; g < 4; g++) {
        const float* p = es[g] + (long long)token * E_;
        x[g][0] = p[tid]; x[g][1] = p[tid + 256];
        float s  = block_sum(x[g][0] + x[g][1], sh);
        float ss = block_sum(x[g][0]*x[g][0] + x[g][1]*x[g][1], sh);
        float m = s * (1.f/512.f);
        float v = ss * (1.f/512.f) - m*m;
        mg[g] = m; rg[g] = rsqrtf(v + 1e-6f);
        stot += s; sstot += ss;
    }
    float m = stot * (1.f/2048.f);
    float r = rsqrtf(sstot * (1.f/2048.f) - m*m + 1e-6f);
    #pragma unroll
    for (int g = 0; g < 4; g++) {
        #pragma unroll
        for (int j = 0; j < 2; j++) {
            int e = tid + j*256;
            float xv = x[g][j];
            cx[((long long)g*BN_ + token)*E_ + e] =
                (xv - mg[g]) * rg[g] * lag[g*E_+e] + lab[g*E_+e];
            ec[(long long)token*C_ + g*E_ + e] =
                (xv - m) * r * lcg[g*E_+e] + lcb[g*E_+e];
        }
    }
}

// ---------------- rowwise LN (FFN) ----------------
__global__ void __launch_bounds__(256) ln_rows_kernel(
    const float* __restrict__ X, const float* __restrict__ gamma,
    const float* __restrict__ beta, float* __restrict__ Y, int rowsPerG)
{
    __shared__ float sh[32];
    long long row = blockIdx.x;
    int tid = threadIdx.x;
    int g = (int)(row / rowsPerG);
    const float* p = X + row * E_;
    float x0 = p[tid], x1 = p[tid+256];
    float s  = block_sum(x0 + x1, sh);
    float ss = block_sum(x0*x0 + x1*x1, sh);
    float m = s * (1.f/512.f);
    float r = rsqrtf(ss * (1.f/512.f) - m*m + 1e-6f);
    float* q = Y + row * E_;
    q[tid]     = (x0 - m) * r * gamma[g*E_+tid]     + beta[g*E_+tid];
    q[tid+256] = (x1 - m) * r * gamma[g*E_+tid+256] + beta[g*E_+tid+256];
}

// ---------------- instance-norm stats over [196,784] per z ----------------
__global__ void __launch_bounds__(256) inorm_stats_kernel(
    const float* __restrict__ attn, float* __restrict__ mean, float* __restrict__ rstd)
{
    __shared__ float sh[32];
    int z = blockIdx.x;
    const float* p = attn + (long long)z * ATTZ_;
    float s = 0.f, ss = 0.f;
    for (int i = threadIdx.x; i < ATTZ_; i += 256) {
        float v = p[i]; s += v; ss += v*v;
    }
    s  = block_sum(s, sh);
    ss = block_sum(ss, sh);
    if (threadIdx.x == 0) {
        float m = s * (1.f/(float)ATTZ_);
        float var = ss * (1.f/(float)ATTZ_) - m*m;
        mean[z] = m;
        rstd[z] = rsqrtf(var + 1e-5f);
    }
}

// ---------------- softmax (optional pre-normalization) ----------------
__global__ void __launch_bounds__(256) softmax_kernel(
    float* __restrict__ S, int cols, int rowsPerZ,
    const float* __restrict__ mean, const float* __restrict__ rstd, float scale)
{
    __shared__ float sh[32];
    long long row = blockIdx.x;
    float* p = S + row * cols;
    float m = 0.f, r = 1.f;
    if (mean) { int z = (int)(row / rowsPerZ); m = mean[z]; r = rstd[z]; }
    int tid = threadIdx.x;
    float vals[4];
    float mx = -INFINITY;
    int cnt = 0;
    for (int i = tid; i < cols; i += 256) {
        float t = mean ? (p[i] - m) * r : p[i] * scale;
        vals[cnt++] = t;
        mx = fmaxf(mx, t);
    }
    mx = block_max(mx, sh);
    float s = 0.f; cnt = 0;
    for (int i = tid; i < cols; i += 256) {
        float e = expf(vals[cnt] - mx);
        vals[cnt++] = e;
        s += e;
    }
    s = block_sum(s, sh);
    float inv = 1.f / s;
    cnt = 0;
    for (int i = tid; i < cols; i += 256) p[i] = vals[cnt++] * inv;
}

// ---------------- small elementwise kernels ----------------
__global__ void transpose_kernel(const float* __restrict__ in, float* __restrict__ out,
                                 int R, int Cc, int batch) {
    long long idx = (long long)blockIdx.x * blockDim.x + threadIdx.x;
    long long total = (long long)batch * R * Cc;
    if (idx >= total) return;
    int b = (int)(idx / ((long long)R*Cc));
    int rem = (int)(idx % ((long long)R*Cc));
    int r = rem / Cc, c = rem % Cc;
    out[(long long)b*R*Cc + (long long)c*R + r] = in[idx];
}

__global__ void reshape_kvs_kernel(const float* __restrict__ that, float* __restrict__ kvs) {
    int idx = blockIdx.x * blockDim.x + threadIdx.x;
    if (idx >= B_*FN_*E_) return;
    int b = idx / FNE_;
    int rem = idx % FNE_;
    int mrow = rem / E_;
    int e = rem % E_;
    int g = mrow / N_, n = mrow % N_;
    kvs[idx] = that[(long long)b*(N_*C_) + (long long)n*C_ + g*E_ + e];
}

__global__ void merge0_kernel(const float* __restrict__ ctx, float* __restrict__ cm0) {
    int idx = blockIdx.x * blockDim.x + threadIdx.x;
    if (idx >= BN_*E_) return;
    int b = idx / NE_;
    int rem = idx % NE_;
    int n = rem / E_;
    int e = rem % E_;
    int h = e >> 6, d = e & 63;
    cm0[idx] = ctx[((long long)(b*H_ + h)*N_ + n)*HD_ + d];
}

// ---------------- SGEMM NN: C = alpha*A@B (+bias)(+gelu)(+res) ----------------
__global__ void __launch_bounds__(256) gemm_nn(
    int M, int Ncol, int K,
    const float* __restrict__ A, int lda,
    const float* __restrict__ B, int ldb,
    float* __restrict__ C, int ldc,
    const float* __restrict__ bias,
    const float* __restrict__ res,
    int act, float alpha,
    int D0, int D1,
    long long sA0, long long sA1, long long sA2,
    long long sB0, long long sB1, long long sB2,
    long long sC0, long long sC1, long long sC2,
    long long sBias0, long long sBias1, long long sBias2,
    long long sR0, long long sR1, long long sR2)
{
    long long z = blockIdx.z;
    int z0 = (int)(z % D0); long long t = z / D0;
    int z1 = (int)(t % D1); int z2 = (int)(t / D1);
    A += z0*sA0 + z1*sA1 + z2*sA2;
    B += z0*sB0 + z1*sB1 + z2*sB2;
    C += z0*sC0 + z1*sC1 + z2*sC2;
    if (bias) bias += z0*sBias0 + z1*sBias1 + z2*sBias2;
    if (res)  res  += z0*sR0 + z1*sR1 + z2*sR2;

    __shared__ float As[8][128];
    __shared__ float Bs[8][128];
    int tid = threadIdx.x;
    int row0 = blockIdx.y * 128;
    int col0 = blockIdx.x * 128;
    int tx = tid & 15, ty = tid >> 4;
    float acc[8][8] = {};
    for (int k0 = 0; k0 < K; k0 += 8) {
        #pragma unroll
        for (int i = 0; i < 4; i++) {
            int idx = tid + i * 256;
            int r = idx >> 3, kk = idx & 7;
            int gr = row0 + r, gk = k0 + kk;
            As[kk][r] = (gr < M && gk < K) ? A[(long long)gr * lda + gk] : 0.f;
        }
        #pragma unroll
        for (int i = 0; i < 4; i++) {
            int idx = tid + i * 256;
            int kk = idx >> 7, cc = idx & 127;
            int gk = k0 + kk, gc = col0 + cc;
            Bs[kk][cc] = (gk < K && gc < Ncol) ? B[(long long)gk * ldb + gc] : 0.f;
        }
        __syncthreads();
        #pragma unroll
        for (int kk = 0; kk < 8; kk++) {
            float4 a0 = *(const float4*)&As[kk][ty * 8];
            float4 a1 = *(const float4*)&As[kk][ty * 8 + 4];
            float4 b0 = *(const float4*)&Bs[kk][tx * 8];
            float4 b1 = *(const float4*)&Bs[kk][tx * 8 + 4];
            float av[8] = {a0.x,a0.y,a0.z,a0.w,a1.x,a1.y,a1.z,a1.w};
            float bv[8] = {b0.x,b0.y,b0.z,b0.w,b1.x,b1.y,b1.z,b1.w};
            #pragma unroll
            for (int i = 0; i < 8; i++)
                #pragma unroll
                for (int j = 0; j < 8; j++)
                    acc[i][j] += av[i] * bv[j];
        }
        __syncthreads();
    }
    #pragma unroll
    for (int i = 0; i < 8; i++) {
        int gr = row0 + ty * 8 + i;
        if (gr >= M) continue;
        #pragma unroll
        for (int j = 0; j < 8; j++) {
            int gc = col0 + tx * 8 + j;
            if (gc >= Ncol) continue;
            float v = acc[i][j] * alpha;
            if (bias) v += bias[gc];
            if (act == 1) v = 0.5f * v * (1.f + erff(v * 0.70710678118654752f));
            if (res) v += res[(long long)gr * ldc + gc];
            C[(long long)gr * ldc + gc] = v;
        }
    }
}

// ---------------- SGEMM NT: C = alpha*A@B^T  (A:MxK lda, B:NxK ldb) ----------------
__global__ void __launch_bounds__(256) gemm_nt(
    int M, int Ncol, int K,
    const float* __restrict__ A, int lda,
    const float* __restrict__ B, int ldb,
    float* __restrict__ C, int ldc,
    float alpha,
    int D0, int D1,
    long long sA0, long long sA1, long long sA2,
    long long sB0, long long sB1, long long sB2,
    long long sC0, long long sC1, long long sC2)
{
    long long z = blockIdx.z;
    int z0 = (int)(z % D0); long long t = z / D0;
    int z1 = (int)(t % D1); int z2 = (int)(t / D1);
    A += z0*sA0 + z1*sA1 + z2*sA2;
    B += z0*sB0 + z1*sB1 + z2*sB2;
    C += z0*sC0 + z1*sC1 + z2*sC2;

    __shared__ float As[8][128];
    __shared__ float Bs[8][128];
    int tid = threadIdx.x;
    int row0 = blockIdx.y * 128;
    int col0 = blockIdx.x * 128;
    int tx = tid & 15, ty = tid >> 4;
    float acc[8][8] = {};
    for (int k0 = 0; k0 < K; k0 += 8) {
        #pragma unroll
        for (int i = 0; i < 4; i++) {
            int idx = tid + i * 256;
            int r = idx >> 3, kk = idx & 7;
            int gr = row0 + r, gk = k0 + kk;
            As[kk][r] = (gr < M && gk < K) ? A[(long long)gr * lda + gk] : 0.f;
        }
        #pragma unroll
        for (int i = 0; i < 4; i++) {
            int idx = tid + i * 256;
            int cc = idx >> 3, kk = idx & 7;
            int gk = k0 + kk, gc = col0 + cc;
            Bs[kk][cc] = (gk < K && gc < Ncol) ? B[(long long)gc * ldb + gk] : 0.f;
        }
        __syncthreads();
        #pragma unroll
        for (int kk = 0; kk < 8; kk++) {
            float4 a0 = *(const float4*)&As[kk][ty * 8];
            float4 a1 = *(const float4*)&As[kk][ty * 8 + 4];
            float4 b0 = *(const float4*)&Bs[kk][tx * 8];
            float4 b1 = *(const float4*)&Bs[kk][tx * 8 + 4];
            float av[8] = {a0.x,a0.y,a0.z,a0.w,a1.x,a1.y,a1.z,a1.w};
            float bv[8] = {b0.x,b0.y,b0.z,b0.w,b1.x,b1.y,b1.z,b1.w};
            #pragma unroll
            for (int i = 0; i < 8; i++)
                #pragma unroll
                for (int j = 0; j < 8; j++)
                    acc[i][j] += av[i] * bv[j];
        }
        __syncthreads();
    }
    #pragma unroll
    for (int i = 0; i < 8; i++) {
        int gr = row0 + ty * 8 + i;
        if (gr >= M) continue;
        #pragma unroll
        for (int j = 0; j < 8; j++) {
            int gc = col0 + tx * 8 + j;
            if (gc >= Ncol) continue;
            C[(long long)gr * ldc + gc] = acc[i][j] * alpha;
        }
    }
}

// ---------------- host launch ----------------
static float* symaddr(const void* sym) {
    void* p = nullptr;
    cudaGetSymbolAddress(&p, sym);
    return (float*)p;
}

extern "C" void kernel_launch(void* const* d_in, const int* in_sizes, int n_in,
                              void* d_out, int out_size) {
    const float* emb[4] = {(const float*)d_in[0], (const float*)d_in[1],
                           (const float*)d_in[2], (const float*)d_in[3]};
    const float* lag  = (const float*)d_in[4];
    const float* lab  = (const float*)d_in[5];
    const float* lcg  = (const float*)d_in[6];
    const float* lcb  = (const float*)d_in[7];
    const float* Wq   = (const float*)d_in[8];
    const float* Wk   = (const float*)d_in[9];
    const float* Wv   = (const float*)d_in[10];
    const float* Wo   = (const float*)d_in[11];
    const float* q_w  = (const float*)d_in[12];
    const float* k_w  = (const float*)d_in[13];
    const float* v_w  = (const float*)d_in[14];
    const float* outw = (const float*)d_in[15];
    const float* lfg  = (const float*)d_in[16];
    const float* lfb  = (const float*)d_in[17];
    const float* fc1w = (const float*)d_in[18];
    const float* fc1b = (const float*)d_in[19];
    const float* fc2w = (const float*)d_in[20];
    const float* fc2b = (const float*)d_in[21];
    float* out = (float*)d_out;

    float* cx   = symaddr(g_cx);
    float* ec   = symaddr(g_ec);
    float* qc   = symaddr(g_qc);
    float* kc   = symaddr(g_kc);
    float* vc   = symaddr(g_vc);
    float* sch  = symaddr(g_sch);
    float* tbuf = symaddr(g_t);
    float* that = symaddr(g_that);
    float* kvs  = symaddr(g_kvs);
    float* Qb   = symaddr(g_Q);
    float* Kb   = symaddr(g_K);
    float* Vb   = symaddr(g_V);
    float* attn = symaddr(g_attn);
    float* meanp= symaddr(g_mean);
    float* rstdp= symaddr(g_rstd);
    float* ctx  = symaddr(g_ctx);
    float* cm0  = symaddr(g_cm0);
    float* hbuf = symaddr(g_h);
    float* xln  = symaddr(g_xln);
    float* x1   = symaddr(g_x1);
    float* qwT  = symaddr(g_qwT);
    float* kwT  = symaddr(g_kwT);
    float* vwT  = symaddr(g_vwT);

    const long long Z = 0;

    // 1. fused LayerNorms
    ln_fused_kernel<<<BN_, 256>>>(emb[0], emb[1], emb[2], emb[3],
                                  lag, lab, lcg, lcb, cx, ec);

    // 2. transpose token-mixing weights
    transpose_kernel<<<(4*N_*N_ + 255)/256, 256>>>(q_w, qwT, N_, N_, 4);
    transpose_kernel<<<(FN_*FN_ + 255)/256, 256>>>(k_w, kwT, FN_, FN_, 1);
    transpose_kernel<<<(FN_*FN_ + 255)/256, 256>>>(v_w, vwT, FN_, FN_, 1);

    // 3. channel projections q,k,v = ec @ W   [3136,2048,2048]
    {
        dim3 g(16, 25, 1);
        gemm_nn<<<g,256>>>(BN_, C_, C_, ec, C_, Wq, C_, qc, C_, nullptr, nullptr, 0, 1.f,
                           1,1, Z,Z,Z, Z,Z,Z, Z,Z,Z, Z,Z,Z, Z,Z,Z);
        gemm_nn<<<g,256>>>(BN_, C_, C_, ec, C_, Wk, C_, kc, C_, nullptr, nullptr, 0, 1.f,
                           1,1, Z,Z,Z, Z,Z,Z, Z,Z,Z, Z,Z,Z, Z,Z,Z);
        gemm_nn<<<g,256>>>(BN_, C_, C_, ec, C_, Wv, C_, vc, C_, nullptr, nullptr, 0, 1.f,
                           1,1, Z,Z,Z, Z,Z,Z, Z,Z,Z, Z,Z,Z, Z,Z,Z);
    }

    // 4. channel attention scores: per (b,h)  [196,196,256]  alpha = 1/sqrt(256)
    {
        dim3 g(2, 2, B_*H_);
        gemm_nt<<<g,256>>>(N_, N_, HDC_, qc, C_, kc, C_, sch, N_, 0.0625f,
                           H_, B_,
                           256LL, (long long)N_*C_, Z,
                           256LL, (long long)N_*C_, Z,
                           (long long)SCHZ_, (long long)H_*SCHZ_, Z);
    }

    // 5. channel softmax over 196
    softmax_kernel<<<B_*H_*N_, 256>>>(sch, N_, 1, nullptr, nullptr, 1.f);

    // 6. T = s @ v  per (b,h) -> [B,N,C]
    {
        dim3 g(2, 2, B_*H_);
        gemm_nn<<<g,256>>>(N_, HDC_, N_, sch, N_, vc, C_, tbuf, C_, nullptr, nullptr, 0, 1.f,
                           H_, B_,
                           (long long)SCHZ_, (long long)H_*SCHZ_, Z,
                           256LL, (long long)N_*C_, Z,
                           256LL, (long long)N_*C_, Z,
                           Z,Z,Z, Z,Z,Z);
    }

    // 7. T_hat = T @ Wo
    {
        dim3 g(16, 25, 1);
        gemm_nn<<<g,256>>>(BN_, C_, C_, tbuf, C_, Wo, C_, that, C_, nullptr, nullptr, 0, 1.f,
                           1,1, Z,Z,Z, Z,Z,Z, Z,Z,Z, Z,Z,Z, Z,Z,Z);
    }

    // 8. KV_S reshape
    reshape_kvs_kernel<<<(B_*FN_*E_ + 255)/256, 256>>>(that, kvs);

    // 9. K = kwT @ KV_S, V = vwT @ KV_S  per batch b  [784,512,784]
    {
        dim3 g(4, 7, B_);
        gemm_nn<<<g,256>>>(FN_, E_, FN_, kwT, FN_, kvs, E_, Kb, E_, nullptr, nullptr, 0, 1.f,
                           B_, 1,
                           Z,Z,Z,
                           (long long)FNE_, Z, Z,
                           (long long)FNE_, Z, Z,
                           Z,Z,Z, Z,Z,Z);
        gemm_nn<<<g,256>>>(FN_, E_, FN_, vwT, FN_, kvs, E_, Vb, E_, nullptr, nullptr, 0, 1.f,
                           B_, 1,
                           Z,Z,Z,
                           (long long)FNE_, Z, Z,
                           (long long)FNE_, Z, Z,
                           Z,Z,Z, Z,Z,Z);
    }

    // 10. Q = qwT[g] @ cx[g,b]  per (g,b)  [196,512,196]
    {
        dim3 g(4, 2, 4*B_);
        gemm_nn<<<g,256>>>(N_, E_, N_, qwT, N_, cx, E_, Qb, E_, nullptr, nullptr, 0, 1.f,
                           B_, 4,
                           Z, (long long)SCHZ_, Z,
                           (long long)NE_, (long long)BNE_, Z,
                           (long long)NE_, (long long)BNE_, Z,
                           Z,Z,Z, Z,Z,Z);
    }

    // 11. spatial logits: per (g,b,h)  [196,784,64]
    {
        dim3 g(7, 2, 512);
        gemm_nt<<<g,256>>>(N_, FN_, HD_, Qb, E_, Kb, E_, attn, FN_, 1.f,
                           H_, B_,
                           64LL, (long long)NE_,  (long long)BNE_,
                           64LL, (long long)FNE_, Z,
                           (long long)ATTZ_, (long long)H_*ATTZ_, (long long)B_*H_*ATTZ_);
    }

    // 12. instance-norm stats per (g,b,h)
    inorm_stats_kernel<<<512, 256>>>(attn, meanp, rstdp);

    // 13. normalized softmax over 784
    softmax_kernel<<<512*N_, 256>>>(attn, FN_, N_, meanp, rstdp, 1.f);

    // 14. ctx = p @ Vh  per (g,b,h)  [196,64,784]
    {
        dim3 g(1, 2, 512);
        gemm_nn<<<g,256>>>(N_, HD_, FN_, attn, FN_, Vb, E_, ctx, HD_, nullptr, nullptr, 0, 1.f,
                           H_, B_,
                           (long long)ATTZ_, (long long)H_*ATTZ_, (long long)B_*H_*ATTZ_,
                           64LL, (long long)FNE_, Z,
                           (long long)(N_*HD_), (long long)(H_*N_*HD_), (long long)(B_*H_*N_*HD_),
                           Z,Z,Z, Z,Z,Z);
    }

    // 15. branch-0 head permute
    merge0_kernel<<<(BN_*E_ + 255)/256, 256>>>(ctx, cm0);

    // 16. out projection + residual-1:  h[g] = emb[g] + cmerged[g] @ out_w[g]
    {
        dim3 g(4, 25, 1);
        for (int gg = 0; gg < 4; gg++) {
            const float* Ag = (gg == 0) ? cm0 : (ctx + (long long)gg * BNE_);
            gemm_nn<<<g,256>>>(BN_, E_, E_, Ag, E_, outw + (long long)gg*E_*E_, E_,
                               hbuf + (long long)gg*BNE_, E_,
                               nullptr, emb[gg], 0, 1.f,
                               1,1, Z,Z,Z, Z,Z,Z, Z,Z,Z, Z,Z,Z, Z,Z,Z);
        }
    }

    // 17. FFN LayerNorm
    ln_rows_kernel<<<4*BN_, 256>>>(hbuf, lfg, lfb, xln, BN_);

    // 18. fc1 + bias + exact GELU  per g  [3136,2048,512]
    {
        dim3 g(16, 25, 4);
        gemm_nn<<<g,256>>>(BN_, 4*E_, E_, xln, E_, fc1w, 4*E_, x1, 4*E_,
                           fc1b, nullptr, 1, 1.f,
                           4, 1,
                           (long long)BNE_, Z, Z,
                           (long long)E_*4*E_, Z, Z,
                           (long long)BN_*4*E_, Z, Z,
                           (long long)4*E_, Z, Z,
                           Z,Z,Z);
    }

    // 19. fc2 + bias + residual-2 -> output  per g  [3136,512,2048]
    {
        dim3 g(4, 25, 4);
        gemm_nn<<<g,256>>>(BN_, E_, 4*E_, x1, 4*E_, fc2w, E_, out, E_,
                           fc2b, hbuf, 0, 1.f,
                           4, 1,
                           (long long)BN_*4*E_, Z, Z,
                           (long long)4*E_*E_, Z, Z,
                           (long long)BNE_, Z, Z,
                           (long long)E_, Z, Z,
                           (long long)BNE_, Z, Z);
    }
}